// round 1
// baseline (speedup 1.0000x reference)
#include <cuda_runtime.h>

// PassiveWaveDigitalMixer — fused 9-point periodic stencil + gated flows.
// B=4, C=128, H=W=256, O=16, M=32 (fixed shapes for this problem).

constexpr int B = 4, C = 128, H = 256, W = 256, O = 16, M = 32;
constexpr float GAIN_CAP = 0.99f;
constexpr float EPS = 1e-4f;

__device__ __forceinline__ float softplus_eps(float p) {
    // stable softplus(p) + EPS
    return fmaxf(p, 0.0f) + log1pf(expf(-fabsf(p))) + EPS;
}

__device__ __forceinline__ float clampg(float v) {
    // cap - relu(cap - relu(v)) == min(max(v,0), cap)
    return fminf(fmaxf(v, 0.0f), GAIN_CAP);
}

__global__ __launch_bounds__(256)
void pwdm_kernel(const float* __restrict__ x,
                 const float* __restrict__ steer,
                 const float* __restrict__ modulation,
                 const float* __restrict__ r_center,
                 const float* __restrict__ r_horizontal,
                 const float* __restrict__ r_vertical,
                 const float* __restrict__ r_diag,
                 const float* __restrict__ gain_h,
                 const float* __restrict__ gain_v,
                 const float* __restrict__ gain_d,
                 const float* __restrict__ steer_w,
                 const float* __restrict__ mod_w,
                 float* __restrict__ out)
{
    __shared__ float s_invh[C], s_invv[C], s_invd[C];
    __shared__ float s_gh[C],   s_gv[C],   s_gd[C];
    __shared__ float s_delta[3];

    const int tx  = threadIdx.x;          // 0..63 : float4 column within row
    const int ty  = threadIdx.y;          // 0..3  : channel sub-lane
    const int tid = ty * 64 + tx;
    const int h   = blockIdx.x;           // 0..255
    const int b   = blockIdx.y;           // 0..3

    // --- per-batch modulation deltas (3 tiny dot products) ---
    if (tid < 3) {
        float acc = 0.0f;
        #pragma unroll
        for (int m = 0; m < M; m++)
            acc = fmaf(modulation[b * M + m], mod_w[tid * M + m], acc);
        s_delta[tid] = tanhf(acc);
    }
    __syncthreads();

    // --- per-channel constants (resistances + modulation-gated gains) ---
    if (tid < C) {
        float spc = softplus_eps(r_center[tid]);
        s_invh[tid] = 1.0f / (spc + softplus_eps(r_horizontal[tid]));
        s_invv[tid] = 1.0f / (spc + softplus_eps(r_vertical[tid]));
        s_invd[tid] = 1.0f / (2.0f * (spc + softplus_eps(r_diag[tid])));
        s_gh[tid] = clampg(tanhf(gain_h[tid]) * (1.0f + 0.1f * s_delta[0]));
        s_gv[tid] = clampg(tanhf(gain_v[tid]) * (1.0f + 0.1f * s_delta[1]));
        s_gd[tid] = clampg(tanhf(gain_d[tid]) * (1.0f + 0.1f * s_delta[2]));
    }

    // --- per-thread steer fields for the 4 w positions (hoisted over c) ---
    float4 a0 = make_float4(0.f, 0.f, 0.f, 0.f);
    float4 a1 = a0, a2 = a0;
    {
        const float4* sp = reinterpret_cast<const float4*>(
            steer + ((size_t)(b * O) * H + h) * W) + tx;
        const int planeF4 = H * W / 4;
        #pragma unroll
        for (int o = 0; o < O; o++) {
            float4 sv = sp[(size_t)o * planeF4];
            float w0 = steer_w[0 * O + o];
            float w1 = steer_w[1 * O + o];
            float w2 = steer_w[2 * O + o];
            a0.x = fmaf(sv.x, w0, a0.x); a0.y = fmaf(sv.y, w0, a0.y);
            a0.z = fmaf(sv.z, w0, a0.z); a0.w = fmaf(sv.w, w0, a0.w);
            a1.x = fmaf(sv.x, w1, a1.x); a1.y = fmaf(sv.y, w1, a1.y);
            a1.z = fmaf(sv.z, w1, a1.z); a1.w = fmaf(sv.w, w1, a1.w);
            a2.x = fmaf(sv.x, w2, a2.x); a2.y = fmaf(sv.y, w2, a2.y);
            a2.z = fmaf(sv.z, w2, a2.z); a2.w = fmaf(sv.w, w2, a2.w);
        }
    }
    // steer multipliers: 1 + 0.2 * tanh(field)
    float4 th, tv, td;
    th.x = fmaf(0.2f, tanhf(a0.x), 1.0f); th.y = fmaf(0.2f, tanhf(a0.y), 1.0f);
    th.z = fmaf(0.2f, tanhf(a0.z), 1.0f); th.w = fmaf(0.2f, tanhf(a0.w), 1.0f);
    tv.x = fmaf(0.2f, tanhf(a1.x), 1.0f); tv.y = fmaf(0.2f, tanhf(a1.y), 1.0f);
    tv.z = fmaf(0.2f, tanhf(a1.z), 1.0f); tv.w = fmaf(0.2f, tanhf(a1.w), 1.0f);
    td.x = fmaf(0.2f, tanhf(a2.x), 1.0f); td.y = fmaf(0.2f, tanhf(a2.y), 1.0f);
    td.z = fmaf(0.2f, tanhf(a2.z), 1.0f); td.w = fmaf(0.2f, tanhf(a2.w), 1.0f);

    __syncthreads();

    const int hu = (h - 1) & (H - 1);
    const int hd = (h + 1) & (H - 1);
    const int w0 = tx * 4;
    const int wl = (w0 - 1) & (W - 1);
    const int wr = (w0 + 4) & (W - 1);

    const size_t batchBase = (size_t)b * C * H * W;
    const int HW = H * W;

    #pragma unroll 4
    for (int c = ty; c < C; c += 4) {
        const float* plane = x + batchBase + (size_t)c * HW;
        const float* rC = plane + h  * W;
        const float* rU = plane + hu * W;
        const float* rD = plane + hd * W;

        float4 cv = reinterpret_cast<const float4*>(rC)[tx];
        float4 uv = reinterpret_cast<const float4*>(rU)[tx];
        float4 dv = reinterpret_cast<const float4*>(rD)[tx];
        float cl = rC[wl], cr = rC[wr];
        float ul = rU[wl], ur = rU[wr];
        float dl = rD[wl], dr = rD[wr];

        float invh = s_invh[c], invv = s_invv[c], invd = s_invd[c];
        float ghc  = s_gh[c],   gvc  = s_gv[c],   gdc  = s_gd[c];

        // horizontal neighbors per lane i
        float L0 = cl,   L1 = cv.x, L2 = cv.y, L3 = cv.z;
        float R0 = cv.y, R1 = cv.z, R2 = cv.w, R3 = cr;
        // diagonal neighbors (up row)
        float UL0 = ul,   UL1 = uv.x, UL2 = uv.y, UL3 = uv.z;
        float UR0 = uv.y, UR1 = uv.z, UR2 = uv.w, UR3 = ur;
        // diagonal neighbors (down row)
        float DL0 = dl,   DL1 = dv.x, DL2 = dv.y, DL3 = dv.z;
        float DR0 = dv.y, DR1 = dv.z, DR2 = dv.w, DR3 = dr;

        float4 o4;
        {
            float fh = (L0 + R0 - 2.0f * cv.x) * invh;
            float fv = (uv.x + dv.x - 2.0f * cv.x) * invv;
            float fd = (UL0 + UR0 + DL0 + DR0 - 4.0f * cv.x) * invd;
            o4.x = cv.x + clampg(ghc * th.x) * fh
                        + clampg(gvc * tv.x) * fv
                        + clampg(gdc * td.x) * fd;
        }
        {
            float fh = (L1 + R1 - 2.0f * cv.y) * invh;
            float fv = (uv.y + dv.y - 2.0f * cv.y) * invv;
            float fd = (UL1 + UR1 + DL1 + DR1 - 4.0f * cv.y) * invd;
            o4.y = cv.y + clampg(ghc * th.y) * fh
                        + clampg(gvc * tv.y) * fv
                        + clampg(gdc * td.y) * fd;
        }
        {
            float fh = (L2 + R2 - 2.0f * cv.z) * invh;
            float fv = (uv.z + dv.z - 2.0f * cv.z) * invv;
            float fd = (UL2 + UR2 + DL2 + DR2 - 4.0f * cv.z) * invd;
            o4.z = cv.z + clampg(ghc * th.z) * fh
                        + clampg(gvc * tv.z) * fv
                        + clampg(gdc * td.z) * fd;
        }
        {
            float fh = (L3 + R3 - 2.0f * cv.w) * invh;
            float fv = (uv.w + dv.w - 2.0f * cv.w) * invv;
            float fd = (UL3 + UR3 + DL3 + DR3 - 4.0f * cv.w) * invd;
            o4.w = cv.w + clampg(ghc * th.w) * fh
                        + clampg(gvc * tv.w) * fv
                        + clampg(gdc * td.w) * fd;
        }

        reinterpret_cast<float4*>(out + batchBase + (size_t)c * HW + h * W)[tx] = o4;
    }
}

extern "C" void kernel_launch(void* const* d_in, const int* in_sizes, int n_in,
                              void* d_out, int out_size)
{
    const float* x            = (const float*)d_in[0];
    const float* steer        = (const float*)d_in[1];
    const float* modulation   = (const float*)d_in[2];
    const float* r_center     = (const float*)d_in[3];
    const float* r_horizontal = (const float*)d_in[4];
    const float* r_vertical   = (const float*)d_in[5];
    const float* r_diag       = (const float*)d_in[6];
    const float* gain_h       = (const float*)d_in[7];
    const float* gain_v       = (const float*)d_in[8];
    const float* gain_d       = (const float*)d_in[9];
    const float* steer_w      = (const float*)d_in[10];
    const float* mod_w        = (const float*)d_in[11];
    float* out = (float*)d_out;

    dim3 block(64, 4, 1);   // 64 float4 columns x 4 channel sub-lanes = 256 thr
    dim3 grid(H, B, 1);     // one block per (h, b) row
    pwdm_kernel<<<grid, block>>>(x, steer, modulation,
                                 r_center, r_horizontal, r_vertical, r_diag,
                                 gain_h, gain_v, gain_d,
                                 steer_w, mod_w, out);
}

// round 2
// speedup vs baseline: 1.2660x; 1.2660x over previous
#include <cuda_runtime.h>

// PassiveWaveDigitalMixer — fused 9-point periodic stencil + gated flows.
// B=4, C=128, H=W=256, O=16, M=32 (fixed shapes).
// R2: one warp covers a full W row (32 lanes x 8 elems); horizontal halos via
// warp shuffles (periodic wrap inside the warp). s = up+down folding halves
// the live stencil registers and shuffles.

constexpr int B = 4, C = 128, H = 256, W = 256, O = 16, M = 32;
constexpr int HW = H * W;
constexpr float GAIN_CAP = 0.99f;
constexpr float EPS = 1e-4f;

__device__ __forceinline__ float softplus_eps(float p) {
    return fmaxf(p, 0.0f) + log1pf(expf(-fabsf(p))) + EPS;
}

__device__ __forceinline__ float clampg(float v) {
    return fminf(fmaxf(v, 0.0f), GAIN_CAP);
}

__global__ __launch_bounds__(256)
void pwdm_kernel(const float* __restrict__ x,
                 const float* __restrict__ steer,
                 const float* __restrict__ modulation,
                 const float* __restrict__ r_center,
                 const float* __restrict__ r_horizontal,
                 const float* __restrict__ r_vertical,
                 const float* __restrict__ r_diag,
                 const float* __restrict__ gain_h,
                 const float* __restrict__ gain_v,
                 const float* __restrict__ gain_d,
                 const float* __restrict__ steer_w,
                 const float* __restrict__ mod_w,
                 float* __restrict__ out)
{
    __shared__ float s_invh[C], s_invv[C], s_invd[C];
    __shared__ float s_gh[C],   s_gv[C],   s_gd[C];
    __shared__ float s_th[W],   s_tv[W],   s_td[W];

    const int tx  = threadIdx.x;          // 0..31 lane (8 w-elems each)
    const int ty  = threadIdx.y;          // 0..7  channel sub-lane
    const int tid = ty * 32 + tx;
    const int h   = blockIdx.x;
    const int b   = blockIdx.y;

    // --- modulation deltas: every thread computes all 3 (broadcast loads) ---
    float d0 = 0.f, d1 = 0.f, d2 = 0.f;
    #pragma unroll
    for (int m = 0; m < M; m++) {
        float mv = modulation[b * M + m];
        d0 = fmaf(mv, mod_w[0 * M + m], d0);
        d1 = fmaf(mv, mod_w[1 * M + m], d1);
        d2 = fmaf(mv, mod_w[2 * M + m], d2);
    }
    d0 = tanhf(d0); d1 = tanhf(d1); d2 = tanhf(d2);

    // --- per-channel constants ---
    if (tid < C) {
        float spc = softplus_eps(r_center[tid]);
        s_invh[tid] = 1.0f / (spc + softplus_eps(r_horizontal[tid]));
        s_invv[tid] = 1.0f / (spc + softplus_eps(r_vertical[tid]));
        s_invd[tid] = 1.0f / (2.0f * (spc + softplus_eps(r_diag[tid])));
        s_gh[tid] = tanhf(gain_h[tid]) * (1.0f + 0.1f * d0);
        s_gv[tid] = tanhf(gain_v[tid]) * (1.0f + 0.1f * d1);
        s_gd[tid] = tanhf(gain_d[tid]) * (1.0f + 0.1f * d2);
    }

    // --- steer fields: thread tid handles w position = tid (coalesced) ---
    {
        float a0 = 0.f, a1 = 0.f, a2 = 0.f;
        const float* sp = steer + ((size_t)b * O * H + h) * W + tid;
        #pragma unroll
        for (int o = 0; o < O; o++) {
            float v = sp[(size_t)o * HW];
            a0 = fmaf(v, steer_w[0 * O + o], a0);
            a1 = fmaf(v, steer_w[1 * O + o], a1);
            a2 = fmaf(v, steer_w[2 * O + o], a2);
        }
        s_th[tid] = fmaf(0.2f, tanhf(a0), 1.0f);
        s_tv[tid] = fmaf(0.2f, tanhf(a1), 1.0f);
        s_td[tid] = fmaf(0.2f, tanhf(a2), 1.0f);
    }
    __syncthreads();

    // --- hoist this lane's 8 steer multipliers into registers ---
    const int w0 = tx * 8;
    float thr[8], tvr[8], tdr[8];
    #pragma unroll
    for (int i = 0; i < 8; i++) {
        thr[i] = s_th[w0 + i];
        tvr[i] = s_tv[w0 + i];
        tdr[i] = s_td[w0 + i];
    }

    const int hu = (h - 1) & (H - 1);
    const int hd = (h + 1) & (H - 1);
    const size_t base = (size_t)b * C * HW + (size_t)ty * HW;
    const float* pC = x + base + (size_t)h  * W + w0;
    const float* pU = x + base + (size_t)hu * W + w0;
    const float* pD = x + base + (size_t)hd * W + w0;
    float*       po = out + base + (size_t)h * W + w0;
    const size_t cstep = (size_t)8 * HW;

    const unsigned FULL = 0xffffffffu;
    const int laneL = (tx + 31) & 31;
    const int laneR = (tx + 1) & 31;

    #pragma unroll 2
    for (int c = ty; c < C; c += 8) {
        float4 cA = *reinterpret_cast<const float4*>(pC);
        float4 cB = *reinterpret_cast<const float4*>(pC + 4);
        float4 uA = *reinterpret_cast<const float4*>(pU);
        float4 uB = *reinterpret_cast<const float4*>(pU + 4);
        float4 dA = *reinterpret_cast<const float4*>(pD);
        float4 dB = *reinterpret_cast<const float4*>(pD + 4);

        // center + (up+down) sums
        float ce[10], se[10];
        ce[1] = cA.x; ce[2] = cA.y; ce[3] = cA.z; ce[4] = cA.w;
        ce[5] = cB.x; ce[6] = cB.y; ce[7] = cB.z; ce[8] = cB.w;
        se[1] = uA.x + dA.x; se[2] = uA.y + dA.y;
        se[3] = uA.z + dA.z; se[4] = uA.w + dA.w;
        se[5] = uB.x + dB.x; se[6] = uB.y + dB.y;
        se[7] = uB.z + dB.z; se[8] = uB.w + dB.w;

        // horizontal halos: periodic wrap is exactly the warp wrap
        ce[0] = __shfl_sync(FULL, ce[8], laneL);
        ce[9] = __shfl_sync(FULL, ce[1], laneR);
        se[0] = __shfl_sync(FULL, se[8], laneL);
        se[9] = __shfl_sync(FULL, se[1], laneR);

        const float invh = s_invh[c], invv = s_invv[c], invd = s_invd[c];
        const float ghc  = s_gh[c],   gvc  = s_gv[c],   gdc  = s_gd[c];

        float o8[8];
        #pragma unroll
        for (int i = 0; i < 8; i++) {
            float cv = ce[i + 1];
            float fh = (ce[i] + ce[i + 2] - 2.0f * cv) * invh;
            float fv = (se[i + 1]          - 2.0f * cv) * invv;
            float fd = (se[i] + se[i + 2]  - 4.0f * cv) * invd;
            float gh = clampg(ghc * thr[i]);
            float gv = clampg(gvc * tvr[i]);
            float gd = clampg(gdc * tdr[i]);
            o8[i] = fmaf(gh, fh, fmaf(gv, fv, fmaf(gd, fd, cv)));
        }

        *reinterpret_cast<float4*>(po)     = make_float4(o8[0], o8[1], o8[2], o8[3]);
        *reinterpret_cast<float4*>(po + 4) = make_float4(o8[4], o8[5], o8[6], o8[7]);

        pC += cstep; pU += cstep; pD += cstep; po += cstep;
    }
}

extern "C" void kernel_launch(void* const* d_in, const int* in_sizes, int n_in,
                              void* d_out, int out_size)
{
    const float* x            = (const float*)d_in[0];
    const float* steer        = (const float*)d_in[1];
    const float* modulation   = (const float*)d_in[2];
    const float* r_center     = (const float*)d_in[3];
    const float* r_horizontal = (const float*)d_in[4];
    const float* r_vertical   = (const float*)d_in[5];
    const float* r_diag       = (const float*)d_in[6];
    const float* gain_h       = (const float*)d_in[7];
    const float* gain_v       = (const float*)d_in[8];
    const float* gain_d       = (const float*)d_in[9];
    const float* steer_w      = (const float*)d_in[10];
    const float* mod_w        = (const float*)d_in[11];
    float* out = (float*)d_out;

    dim3 block(32, 8, 1);   // one warp per full W row, 8 channel sub-lanes
    dim3 grid(H, B, 1);     // one block per (h, b)
    pwdm_kernel<<<grid, block>>>(x, steer, modulation,
                                 r_center, r_horizontal, r_vertical, r_diag,
                                 gain_h, gain_v, gain_d,
                                 steer_w, mod_w, out);
}